// round 1
// baseline (speedup 1.0000x reference)
#include <cuda_runtime.h>
#include <cuda_bf16.h>
#include <math.h>

// ---------------- problem dims (fixed by dataset) ----------------
#define LL     1024
#define BB     4
#define FF     128
#define DD     1024
#define DI     2048
#define NST    16
#define KCONV  4
#define RR     64
#define HH     2048
#define NOUT   10
#define NLAYER 4
#define MROWS  (BB*LL)      // 4096 tokens, layout t = b*L + l
#define SEP    512
#define MDEC   ((LL-SEP)*BB) // 2048 decoder rows

// ---------------- scratch (device globals; no allocations allowed) ----------------
__device__ float g_xT  [MROWS*FF];        // gathered x_src in (b,l) order
__device__ float g_h   [MROWS*DD];        // mixer output / encoder output
__device__ float g_res [MROWS*DD];        // residual stream
__device__ float g_hn  [MROWS*DD];        // layernorm output
__device__ float g_xz  [MROWS*(2*DI)];    // in_proj output (xin | z)
__device__ float g_xc  [MROWS*DI];        // conv+silu output
__device__ float g_xdbl[MROWS*(RR+2*NST)];// x_proj output (dt_raw | B | C)
__device__ float g_dt  [MROWS*DI];        // softplus dt
__device__ float g_y   [MROWS*DI];        // scan output (fused epilogue)
__device__ float g_dec [MDEC*DD];         // gathered decoder input
__device__ float g_mid [MDEC*HH];         // gelu(dec1)

// ---------------- generic fp32 SGEMM: C = A(MxK) * B(NxK)^T (+bias, act) ----------------
#define BM 128
#define BN 128
#define BK 16

template<int ACT>   // 0 = none, 1 = softplus, 2 = gelu
__global__ __launch_bounds__(256)
void sgemm_tn(const float* __restrict__ A, const float* __restrict__ B,
              const float* __restrict__ bias, float* __restrict__ C,
              int M, int N, int K, int lda, int ldb, int ldc)
{
    __shared__ __align__(16) float As[BK][BM];
    __shared__ __align__(16) float Bs[BK][BN];

    const int tid = threadIdx.x;
    const int tx  = tid & 15;    // N direction (16)
    const int ty  = tid >> 4;    // M direction (16)
    const int rowBase = blockIdx.y * BM;
    const int colBase = blockIdx.x * BN;

    float acc[8][8];
    #pragma unroll
    for (int i = 0; i < 8; i++)
        #pragma unroll
        for (int j = 0; j < 8; j++) acc[i][j] = 0.f;

    const int ktiles = K / BK;   // all K are multiples of 16 here
    for (int kt = 0; kt < ktiles; ++kt) {
        const int k0 = kt * BK;
        #pragma unroll
        for (int ld = 0; ld < 2; ++ld) {
            int i  = tid + ld * 256;          // 0..511 float4 slots
            int r  = i >> 2;                  // 0..127
            int kc = (i & 3) * 4;             // 0,4,8,12
            int gr = rowBase + r;
            float4 v = make_float4(0.f, 0.f, 0.f, 0.f);
            if (gr < M) v = *reinterpret_cast<const float4*>(A + (size_t)gr * lda + k0 + kc);
            As[kc+0][r] = v.x; As[kc+1][r] = v.y; As[kc+2][r] = v.z; As[kc+3][r] = v.w;
        }
        #pragma unroll
        for (int ld = 0; ld < 2; ++ld) {
            int i  = tid + ld * 256;
            int r  = i >> 2;
            int kc = (i & 3) * 4;
            int gr = colBase + r;
            float4 v = make_float4(0.f, 0.f, 0.f, 0.f);
            if (gr < N) v = *reinterpret_cast<const float4*>(B + (size_t)gr * ldb + k0 + kc);
            Bs[kc+0][r] = v.x; Bs[kc+1][r] = v.y; Bs[kc+2][r] = v.z; Bs[kc+3][r] = v.w;
        }
        __syncthreads();

        #pragma unroll
        for (int kk = 0; kk < BK; ++kk) {
            float ar[8], br[8];
            *reinterpret_cast<float4*>(&ar[0]) = *reinterpret_cast<const float4*>(&As[kk][ty*8]);
            *reinterpret_cast<float4*>(&ar[4]) = *reinterpret_cast<const float4*>(&As[kk][ty*8+4]);
            *reinterpret_cast<float4*>(&br[0]) = *reinterpret_cast<const float4*>(&Bs[kk][tx*8]);
            *reinterpret_cast<float4*>(&br[4]) = *reinterpret_cast<const float4*>(&Bs[kk][tx*8+4]);
            #pragma unroll
            for (int i = 0; i < 8; i++)
                #pragma unroll
                for (int j = 0; j < 8; j++) acc[i][j] += ar[i] * br[j];
        }
        __syncthreads();
    }

    #pragma unroll
    for (int i = 0; i < 8; i++) {
        int r = rowBase + ty * 8 + i;
        if (r >= M) continue;
        #pragma unroll
        for (int j = 0; j < 8; j++) {
            int c = colBase + tx * 8 + j;
            if (c >= N) continue;
            float v = acc[i][j];
            if (bias) v += bias[c];
            if (ACT == 1) {   // softplus (stable)
                v = fmaxf(v, 0.f) + log1pf(__expf(-fabsf(v)));
            } else if (ACT == 2) { // exact gelu
                v = 0.5f * v * (1.f + erff(v * 0.70710678118654752f));
            }
            C[(size_t)r * ldc + c] = v;
        }
    }
}

// ---------------- elementwise / helper kernels ----------------

// gather x_src (L,B,F) -> (b,l) row order
__global__ void gather_x_kernel(const float* __restrict__ x_src)
{
    int idx = blockIdx.x * blockDim.x + threadIdx.x;
    if (idx >= MROWS * FF) return;
    int t = idx >> 7, f = idx & 127;
    int b = t >> 10, l = t & 1023;
    g_xT[idx] = x_src[(l * BB + b) * FF + f];
}

// add y encoder for l < sep:  h += y_src[l,b]*yenc_w[d] + yenc_b[d]
__global__ void add_yenc_kernel(const float* __restrict__ y_src,
                                const float* __restrict__ yenc_w,
                                const float* __restrict__ yenc_b)
{
    int idx = blockIdx.x * blockDim.x + threadIdx.x;
    if (idx >= MROWS * DD) return;
    int t = idx >> 10, d = idx & 1023;
    int b = t >> 10, l = t & 1023;
    if (l < SEP)
        g_h[idx] += y_src[l * BB + b] * yenc_w[d] + yenc_b[d];
}

// residual update + layernorm:  res = h (+ res);  hn = LN(res)*w + b
__global__ __launch_bounds__(256)
void resln_kernel(const float* __restrict__ h, float* __restrict__ res,
                  float* __restrict__ out, const float* __restrict__ w,
                  const float* __restrict__ bb, int first)
{
    __shared__ float sbuf[256];
    int row = blockIdx.x;
    int tid = threadIdx.x;
    float v[4];
    float s = 0.f;
    #pragma unroll
    for (int j = 0; j < 4; j++) {
        int c = tid + j * 256;
        size_t idx = (size_t)row * DD + c;
        float x = h[idx];
        if (!first) x += res[idx];
        res[idx] = x;
        v[j] = x;
        s += x;
    }
    sbuf[tid] = s; __syncthreads();
    for (int st = 128; st > 0; st >>= 1) { if (tid < st) sbuf[tid] += sbuf[tid + st]; __syncthreads(); }
    float mean = sbuf[0] * (1.f / DD);
    __syncthreads();
    float s2 = 0.f;
    #pragma unroll
    for (int j = 0; j < 4; j++) { float dv = v[j] - mean; s2 += dv * dv; }
    sbuf[tid] = s2; __syncthreads();
    for (int st = 128; st > 0; st >>= 1) { if (tid < st) sbuf[tid] += sbuf[tid + st]; __syncthreads(); }
    float rstd = rsqrtf(sbuf[0] * (1.f / DD) + 1e-5f);
    #pragma unroll
    for (int j = 0; j < 4; j++) {
        int c = tid + j * 256;
        out[(size_t)row * DD + c] = (v[j] - mean) * rstd * w[c] + bb[c];
    }
}

// causal depthwise conv (K=4) + silu, reading xin = g_xz[..., :DI]
__global__ void conv_silu_kernel(const float* __restrict__ cw, const float* __restrict__ cb)
{
    int idx = blockIdx.x * blockDim.x + threadIdx.x;
    if (idx >= MROWS * DI) return;
    int d = idx & (DI - 1);
    int t = idx >> 11;
    int b = t >> 10, l = t & 1023;
    const float* base = g_xz + (size_t)(b << 10) * (2 * DI) + d;
    float w0 = cw[d*4+0], w1 = cw[d*4+1], w2 = cw[d*4+2], w3 = cw[d*4+3];
    float v = cb[d];
    v += w3 * base[(size_t)l * (2*DI)];
    if (l >= 1) v += w2 * base[(size_t)(l-1) * (2*DI)];
    if (l >= 2) v += w1 * base[(size_t)(l-2) * (2*DI)];
    if (l >= 3) v += w0 * base[(size_t)(l-3) * (2*DI)];
    g_xc[idx] = v / (1.f + __expf(-v));   // silu
}

// selective scan: one thread per (b,d) channel; fused D-skip + silu(z) gate epilogue
__global__ __launch_bounds__(256)
void scan_kernel(const float* __restrict__ A_log, const float* __restrict__ Dss)
{
    int gid = blockIdx.x * blockDim.x + threadIdx.x;   // 0..8191
    if (gid >= BB * DI) return;
    int b = gid >> 11;
    int d = gid & (DI - 1);

    float Ac[NST], hs[NST];
    #pragma unroll
    for (int n = 0; n < NST; n++) {
        Ac[n] = -__expf(A_log[d * NST + n]);
        hs[n] = 0.f;
    }
    float Dd = Dss[d];

    for (int l = 0; l < LL; l++) {
        int t = (b << 10) + l;
        float dtv = g_dt[(size_t)t * DI + d];
        float xv  = g_xc[(size_t)t * DI + d];
        const float* bc = g_xdbl + (size_t)t * (RR + 2*NST) + RR;
        float dtx = dtv * xv;
        float acc = 0.f;
        #pragma unroll
        for (int n = 0; n < NST; n++) {
            float dA = __expf(dtv * Ac[n]);
            hs[n] = hs[n] * dA + dtx * bc[n];
            acc += hs[n] * bc[NST + n];
        }
        float zv = g_xz[(size_t)t * (2*DI) + DI + d];
        float gate = zv / (1.f + __expf(-zv));
        g_y[(size_t)t * DI + d] = (acc + Dd * xv) * gate;
    }
}

// gather final-LN rows with l >= SEP into decoder order r = (l-SEP)*B + b
__global__ void gather_dec_kernel()
{
    int idx = blockIdx.x * blockDim.x + threadIdx.x;
    if (idx >= MDEC * DD) return;
    int r = idx >> 10, d = idx & 1023;
    int b = r & 3;
    int l = SEP + (r >> 2);
    g_dec[idx] = g_hn[((size_t)b * LL + l) * DD + d];
}

// final tiny head: out[r, o] = mid[r,:] . dec2_w[o,:] + dec2_b[o]   (one warp per row)
__global__ __launch_bounds__(256)
void dec2_kernel(const float* __restrict__ w, const float* __restrict__ bias,
                 float* __restrict__ out)
{
    int warp = (blockIdx.x * blockDim.x + threadIdx.x) >> 5;
    int lane = threadIdx.x & 31;
    if (warp >= MDEC) return;
    float acc[NOUT];
    #pragma unroll
    for (int o = 0; o < NOUT; o++) acc[o] = 0.f;
    const float* a = g_mid + (size_t)warp * HH;
    for (int k = lane; k < HH; k += 32) {
        float av = a[k];
        #pragma unroll
        for (int o = 0; o < NOUT; o++) acc[o] += av * w[o * HH + k];
    }
    #pragma unroll
    for (int o = 0; o < NOUT; o++) {
        #pragma unroll
        for (int sh = 16; sh > 0; sh >>= 1)
            acc[o] += __shfl_down_sync(0xffffffffu, acc[o], sh);
    }
    if (lane == 0) {
        #pragma unroll
        for (int o = 0; o < NOUT; o++) out[warp * NOUT + o] = acc[o] + bias[o];
    }
}

// ---------------- host orchestration ----------------
static inline dim3 gemm_grid(int M, int N) {
    return dim3((N + BN - 1) / BN, (M + BM - 1) / BM);
}

template<typename T> static float* devptr(T& sym) {
    void* p = nullptr;
    cudaGetSymbolAddress(&p, sym);
    return (float*)p;
}

extern "C" void kernel_launch(void* const* d_in, const int* in_sizes, int n_in,
                              void* d_out, int out_size)
{
    const float* x_src    = (const float*)d_in[0];
    const float* y_src    = (const float*)d_in[1];
    const float* enc_w    = (const float*)d_in[2];
    const float* enc_b    = (const float*)d_in[3];
    const float* yenc_w   = (const float*)d_in[4];
    const float* yenc_b   = (const float*)d_in[5];
    const float* norm_w   = (const float*)d_in[6];
    const float* norm_b   = (const float*)d_in[7];
    const float* in_proj_w= (const float*)d_in[8];
    const float* conv_w   = (const float*)d_in[9];
    const float* conv_b   = (const float*)d_in[10];
    const float* x_proj_w = (const float*)d_in[11];
    const float* dt_w     = (const float*)d_in[12];
    const float* dt_b     = (const float*)d_in[13];
    const float* A_log    = (const float*)d_in[14];
    const float* D_ssm    = (const float*)d_in[15];
    const float* out_w    = (const float*)d_in[16];
    const float* normf_w  = (const float*)d_in[17];
    const float* normf_b  = (const float*)d_in[18];
    const float* dec1_w   = (const float*)d_in[19];
    const float* dec1_b   = (const float*)d_in[20];
    const float* dec2_w   = (const float*)d_in[21];
    const float* dec2_b   = (const float*)d_in[22];
    float* out = (float*)d_out;

    float* p_xT   = devptr(g_xT);
    float* p_h    = devptr(g_h);
    float* p_res  = devptr(g_res);
    float* p_hn   = devptr(g_hn);
    float* p_xz   = devptr(g_xz);
    float* p_xc   = devptr(g_xc);
    float* p_xdbl = devptr(g_xdbl);
    float* p_dt   = devptr(g_dt);
    float* p_y    = devptr(g_y);
    float* p_dec  = devptr(g_dec);
    float* p_mid  = devptr(g_mid);

    // 1) gather x into (b,l) order, encoder GEMM (+enc_b), add y-encoder
    gather_x_kernel<<<(MROWS*FF + 255)/256, 256>>>(x_src);
    sgemm_tn<0><<<gemm_grid(MROWS, DD), 256>>>(p_xT, enc_w, enc_b, p_h,
                                               MROWS, DD, FF, FF, FF, DD);
    add_yenc_kernel<<<(MROWS*DD + 255)/256, 256>>>(y_src, yenc_w, yenc_b);

    // 2) mamba layers
    for (int i = 0; i < NLAYER; i++) {
        resln_kernel<<<MROWS, 256>>>(p_h, p_res, p_hn,
                                     norm_w + i*DD, norm_b + i*DD, i == 0);
        // in_proj: (M,D) x (2Di,D)^T -> (M,2Di)
        sgemm_tn<0><<<gemm_grid(MROWS, 2*DI), 256>>>(
            p_hn, in_proj_w + (size_t)i * (2*DI) * DD, nullptr, p_xz,
            MROWS, 2*DI, DD, DD, DD, 2*DI);
        // causal conv + silu
        conv_silu_kernel<<<(MROWS*DI + 255)/256, 256>>>(conv_w + i*DI*KCONV, conv_b + i*DI);
        // x_proj: (M,Di) x (96,Di)^T -> (M,96)
        sgemm_tn<0><<<gemm_grid(MROWS, RR + 2*NST), 256>>>(
            p_xc, x_proj_w + (size_t)i * (RR + 2*NST) * DI, nullptr, p_xdbl,
            MROWS, RR + 2*NST, DI, DI, DI, RR + 2*NST);
        // dt proj + softplus: (M,64) x (Di,64)^T -> (M,Di)
        sgemm_tn<1><<<gemm_grid(MROWS, DI), 256>>>(
            p_xdbl, dt_w + (size_t)i * DI * RR, dt_b + i*DI, p_dt,
            MROWS, DI, RR, RR + 2*NST, RR, DI);
        // selective scan with fused epilogue -> g_y
        scan_kernel<<<(BB*DI + 255)/256, 256>>>(A_log + (size_t)i * DI * NST, D_ssm + i*DI);
        // out proj: (M,Di) x (D,Di)^T -> (M,D) -> g_h
        sgemm_tn<0><<<gemm_grid(MROWS, DD), 256>>>(
            p_y, out_w + (size_t)i * DD * DI, nullptr, p_h,
            MROWS, DD, DI, DI, DI, DD);
    }

    // 3) final residual + LN
    resln_kernel<<<MROWS, 256>>>(p_h, p_res, p_hn, normf_w, normf_b, 0);

    // 4) decoder (only rows l >= SEP)
    gather_dec_kernel<<<(MDEC*DD + 255)/256, 256>>>();
    sgemm_tn<2><<<gemm_grid(MDEC, HH), 256>>>(p_dec, dec1_w, dec1_b, p_mid,
                                              MDEC, HH, DD, DD, DD, HH);
    dec2_kernel<<<(MDEC*32 + 255)/256, 256>>>(dec2_w, dec2_b, out);
}

// round 2
// speedup vs baseline: 1.6076x; 1.6076x over previous
#include <cuda_runtime.h>
#include <cuda_bf16.h>
#include <math.h>

// ---------------- problem dims (fixed by dataset) ----------------
#define LL     1024
#define BB     4
#define FF     128
#define DD     1024
#define DI     2048
#define NST    16
#define KCONV  4
#define RR     64
#define HH     2048
#define NOUT   10
#define NLAYER 4
#define MROWS  (BB*LL)      // 4096 tokens, layout t = b*L + l
#define SEP    512
#define MDEC   ((LL-SEP)*BB) // 2048 decoder rows

// ---------------- scratch (device globals; no allocations allowed) ----------------
__device__ float g_xT  [MROWS*FF];
__device__ float g_h   [MROWS*DD];
__device__ float g_res [MROWS*DD];
__device__ float g_hn  [MROWS*DD];
__device__ float g_xz  [MROWS*(2*DI)];
__device__ float g_xc  [MROWS*DI];
__device__ float g_xdbl[MROWS*(RR+2*NST)];
__device__ float g_dt  [MROWS*DI];
__device__ float g_y   [MROWS*DI];
__device__ float g_dec [MDEC*DD];
__device__ float g_mid [MDEC*HH];

// ---------------- TF32 tensor-core GEMM: C = A(MxK) * B(NxK)^T (+bias, act) ----------------
#define BM 128
#define BN 128
#define BK 16
#define LDSA 20   // padded row pitch (floats): conflict-free LDSM bank mapping

__device__ __forceinline__ unsigned f2tf32(float f) {
    unsigned u;
    asm("cvt.rna.tf32.f32 %0, %1;" : "=r"(u) : "f"(f));
    return u;
}

__device__ __forceinline__ void ldsm_x4(unsigned& d0, unsigned& d1, unsigned& d2, unsigned& d3,
                                        unsigned addr) {
    asm volatile("ldmatrix.sync.aligned.m8n8.x4.shared.b16 {%0,%1,%2,%3}, [%4];"
                 : "=r"(d0), "=r"(d1), "=r"(d2), "=r"(d3) : "r"(addr));
}

__device__ __forceinline__ void mma_tf32(float* c, const unsigned* a, const unsigned* b) {
    asm volatile("mma.sync.aligned.m16n8k8.row.col.f32.tf32.tf32.f32 "
                 "{%0,%1,%2,%3}, {%4,%5,%6,%7}, {%8,%9}, {%0,%1,%2,%3};"
                 : "+f"(c[0]), "+f"(c[1]), "+f"(c[2]), "+f"(c[3])
                 : "r"(a[0]), "r"(a[1]), "r"(a[2]), "r"(a[3]), "r"(b[0]), "r"(b[1]));
}

template<int ACT>   // 0 = none, 1 = softplus, 2 = gelu
__global__ __launch_bounds__(256)
void tgemm_tn(const float* __restrict__ A, const float* __restrict__ B,
              const float* __restrict__ bias, float* __restrict__ C,
              int M, int N, int K, int lda, int ldb, int ldc)
{
    __shared__ __align__(16) float As[BM * LDSA];
    __shared__ __align__(16) float Bs[BN * LDSA];

    const int tid  = threadIdx.x;
    const int lane = tid & 31;
    const int warp = tid >> 5;
    const int wm = (warp >> 2) * 64;   // warp M offset within tile
    const int wn = (warp & 3) * 32;    // warp N offset within tile
    const int rowBase = blockIdx.y * BM;
    const int colBase = blockIdx.x * BN;

    float acc[4][4][4];
    #pragma unroll
    for (int mi = 0; mi < 4; mi++)
        #pragma unroll
        for (int ni = 0; ni < 4; ni++)
            #pragma unroll
            for (int e = 0; e < 4; e++) acc[mi][ni][e] = 0.f;

    // per-thread gmem load coords (2 float4 for A, 2 for B per K-tile)
    // i = tid + ld*256 -> r = i>>2 (0..127), kc = (i&3)*4
    float4 pa[2], pb[2];
    const int ktiles = K / BK;

    // prefetch tile 0
    #pragma unroll
    for (int ld = 0; ld < 2; ld++) {
        int i = tid + ld * 256;
        int r = i >> 2, kc = (i & 3) * 4;
        int gr = rowBase + r;
        pa[ld] = make_float4(0.f, 0.f, 0.f, 0.f);
        if (gr < M) pa[ld] = *reinterpret_cast<const float4*>(A + (size_t)gr * lda + kc);
        int gc = colBase + r;
        pb[ld] = make_float4(0.f, 0.f, 0.f, 0.f);
        if (gc < N) pb[ld] = *reinterpret_cast<const float4*>(B + (size_t)gc * ldb + kc);
    }

    // ldmatrix address precompute
    const int jr = lane >> 3;      // matrix index 0..3
    const int r8 = lane & 7;       // row within matrix
    // A: row = wm + mi*16 + ((jr&1)<<3) + r8, col = k0 + ((jr>>1)<<2)
    const int a_row = wm + ((jr & 1) << 3) + r8;
    const int a_col = (jr >> 1) << 2;
    // B: row = wn + np*16 + ((jr>>1)<<3) + r8, col = k0 + ((jr&1)<<2)
    const int b_row = wn + ((jr >> 1) << 3) + r8;
    const int b_col = (jr & 1) << 2;

    unsigned sA = (unsigned)__cvta_generic_to_shared(As);
    unsigned sB = (unsigned)__cvta_generic_to_shared(Bs);

    for (int kt = 0; kt < ktiles; ++kt) {
        // store staged regs -> smem (with tf32 rounding)
        #pragma unroll
        for (int ld = 0; ld < 2; ld++) {
            int i = tid + ld * 256;
            int r = i >> 2, kc = (i & 3) * 4;
            unsigned* da = reinterpret_cast<unsigned*>(&As[r * LDSA + kc]);
            da[0] = f2tf32(pa[ld].x); da[1] = f2tf32(pa[ld].y);
            da[2] = f2tf32(pa[ld].z); da[3] = f2tf32(pa[ld].w);
            unsigned* db = reinterpret_cast<unsigned*>(&Bs[r * LDSA + kc]);
            db[0] = f2tf32(pb[ld].x); db[1] = f2tf32(pb[ld].y);
            db[2] = f2tf32(pb[ld].z); db[3] = f2tf32(pb[ld].w);
        }
        __syncthreads();

        // prefetch next tile to regs
        if (kt + 1 < ktiles) {
            const int k0n = (kt + 1) * BK;
            #pragma unroll
            for (int ld = 0; ld < 2; ld++) {
                int i = tid + ld * 256;
                int r = i >> 2, kc = (i & 3) * 4;
                int gr = rowBase + r;
                pa[ld] = make_float4(0.f, 0.f, 0.f, 0.f);
                if (gr < M) pa[ld] = *reinterpret_cast<const float4*>(A + (size_t)gr * lda + k0n + kc);
                int gc = colBase + r;
                pb[ld] = make_float4(0.f, 0.f, 0.f, 0.f);
                if (gc < N) pb[ld] = *reinterpret_cast<const float4*>(B + (size_t)gc * ldb + k0n + kc);
            }
        }

        // compute 2 k8 slices
        #pragma unroll
        for (int ks = 0; ks < 2; ks++) {
            const int k0 = ks * 8;
            unsigned afr[4][4];
            #pragma unroll
            for (int mi = 0; mi < 4; mi++) {
                unsigned addr = sA + ((a_row + mi * 16) * LDSA + k0 + a_col) * 4;
                ldsm_x4(afr[mi][0], afr[mi][1], afr[mi][2], afr[mi][3], addr);
            }
            unsigned bfr[4][2];
            #pragma unroll
            for (int np = 0; np < 2; np++) {
                unsigned addr = sB + ((b_row + np * 16) * LDSA + k0 + b_col) * 4;
                ldsm_x4(bfr[np*2][0], bfr[np*2][1], bfr[np*2+1][0], bfr[np*2+1][1], addr);
            }
            #pragma unroll
            for (int mi = 0; mi < 4; mi++)
                #pragma unroll
                for (int ni = 0; ni < 4; ni++)
                    mma_tf32(acc[mi][ni], afr[mi], bfr[ni]);
        }
        __syncthreads();
    }

    // epilogue
    const int rg = lane >> 2;
    const int cg = (lane & 3) * 2;
    #pragma unroll
    for (int mi = 0; mi < 4; mi++) {
        #pragma unroll
        for (int ni = 0; ni < 4; ni++) {
            #pragma unroll
            for (int e = 0; e < 4; e++) {
                int r = rowBase + wm + mi * 16 + rg + ((e >> 1) << 3);
                int c = colBase + wn + ni * 8 + cg + (e & 1);
                if (r >= M || c >= N) continue;
                float v = acc[mi][ni][e];
                if (bias) v += bias[c];
                if (ACT == 1) {
                    v = fmaxf(v, 0.f) + log1pf(__expf(-fabsf(v)));
                } else if (ACT == 2) {
                    v = 0.5f * v * (1.f + erff(v * 0.70710678118654752f));
                }
                C[(size_t)r * ldc + c] = v;
            }
        }
    }
}

// ---------------- elementwise / helper kernels ----------------

__global__ void gather_x_kernel(const float* __restrict__ x_src)
{
    int idx = blockIdx.x * blockDim.x + threadIdx.x;
    if (idx >= MROWS * FF) return;
    int t = idx >> 7, f = idx & 127;
    int b = t >> 10, l = t & 1023;
    g_xT[idx] = x_src[(l * BB + b) * FF + f];
}

__global__ void add_yenc_kernel(const float* __restrict__ y_src,
                                const float* __restrict__ yenc_w,
                                const float* __restrict__ yenc_b)
{
    int idx = blockIdx.x * blockDim.x + threadIdx.x;
    if (idx >= MROWS * DD) return;
    int t = idx >> 10, d = idx & 1023;
    int b = t >> 10, l = t & 1023;
    if (l < SEP)
        g_h[idx] += y_src[l * BB + b] * yenc_w[d] + yenc_b[d];
}

__global__ __launch_bounds__(256)
void resln_kernel(const float* __restrict__ h, float* __restrict__ res,
                  float* __restrict__ out, const float* __restrict__ w,
                  const float* __restrict__ bb, int first)
{
    __shared__ float sbuf[256];
    int row = blockIdx.x;
    int tid = threadIdx.x;
    float v[4];
    float s = 0.f;
    #pragma unroll
    for (int j = 0; j < 4; j++) {
        int c = tid + j * 256;
        size_t idx = (size_t)row * DD + c;
        float x = h[idx];
        if (!first) x += res[idx];
        res[idx] = x;
        v[j] = x;
        s += x;
    }
    sbuf[tid] = s; __syncthreads();
    for (int st = 128; st > 0; st >>= 1) { if (tid < st) sbuf[tid] += sbuf[tid + st]; __syncthreads(); }
    float mean = sbuf[0] * (1.f / DD);
    __syncthreads();
    float s2 = 0.f;
    #pragma unroll
    for (int j = 0; j < 4; j++) { float dv = v[j] - mean; s2 += dv * dv; }
    sbuf[tid] = s2; __syncthreads();
    for (int st = 128; st > 0; st >>= 1) { if (tid < st) sbuf[tid] += sbuf[tid + st]; __syncthreads(); }
    float rstd = rsqrtf(sbuf[0] * (1.f / DD) + 1e-5f);
    #pragma unroll
    for (int j = 0; j < 4; j++) {
        int c = tid + j * 256;
        out[(size_t)row * DD + c] = (v[j] - mean) * rstd * w[c] + bb[c];
    }
}

__global__ void conv_silu_kernel(const float* __restrict__ cw, const float* __restrict__ cb)
{
    int idx = blockIdx.x * blockDim.x + threadIdx.x;
    if (idx >= MROWS * DI) return;
    int d = idx & (DI - 1);
    int t = idx >> 11;
    int b = t >> 10, l = t & 1023;
    const float* base = g_xz + (size_t)(b << 10) * (2 * DI) + d;
    float w0 = cw[d*4+0], w1 = cw[d*4+1], w2 = cw[d*4+2], w3 = cw[d*4+3];
    float v = cb[d];
    v += w3 * base[(size_t)l * (2*DI)];
    if (l >= 1) v += w2 * base[(size_t)(l-1) * (2*DI)];
    if (l >= 2) v += w1 * base[(size_t)(l-2) * (2*DI)];
    if (l >= 3) v += w0 * base[(size_t)(l-3) * (2*DI)];
    g_xc[idx] = v / (1.f + __expf(-v));
}

__global__ __launch_bounds__(256)
void scan_kernel(const float* __restrict__ A_log, const float* __restrict__ Dss)
{
    int gid = blockIdx.x * blockDim.x + threadIdx.x;
    if (gid >= BB * DI) return;
    int b = gid >> 11;
    int d = gid & (DI - 1);

    float Ac[NST], hs[NST];
    #pragma unroll
    for (int n = 0; n < NST; n++) {
        Ac[n] = -__expf(A_log[d * NST + n]);
        hs[n] = 0.f;
    }
    float Dd = Dss[d];

    for (int l = 0; l < LL; l++) {
        int t = (b << 10) + l;
        float dtv = g_dt[(size_t)t * DI + d];
        float xv  = g_xc[(size_t)t * DI + d];
        const float* bc = g_xdbl + (size_t)t * (RR + 2*NST) + RR;
        float dtx = dtv * xv;
        float accv = 0.f;
        #pragma unroll
        for (int n = 0; n < NST; n++) {
            float dA = __expf(dtv * Ac[n]);
            hs[n] = hs[n] * dA + dtx * bc[n];
            accv += hs[n] * bc[NST + n];
        }
        float zv = g_xz[(size_t)t * (2*DI) + DI + d];
        float gate = zv / (1.f + __expf(-zv));
        g_y[(size_t)t * DI + d] = (accv + Dd * xv) * gate;
    }
}

__global__ void gather_dec_kernel()
{
    int idx = blockIdx.x * blockDim.x + threadIdx.x;
    if (idx >= MDEC * DD) return;
    int r = idx >> 10, d = idx & 1023;
    int b = r & 3;
    int l = SEP + (r >> 2);
    g_dec[idx] = g_hn[((size_t)b * LL + l) * DD + d];
}

__global__ __launch_bounds__(256)
void dec2_kernel(const float* __restrict__ w, const float* __restrict__ bias,
                 float* __restrict__ out)
{
    int warp = (blockIdx.x * blockDim.x + threadIdx.x) >> 5;
    int lane = threadIdx.x & 31;
    if (warp >= MDEC) return;
    float acc[NOUT];
    #pragma unroll
    for (int o = 0; o < NOUT; o++) acc[o] = 0.f;
    const float* a = g_mid + (size_t)warp * HH;
    for (int k = lane; k < HH; k += 32) {
        float av = a[k];
        #pragma unroll
        for (int o = 0; o < NOUT; o++) acc[o] += av * w[o * HH + k];
    }
    #pragma unroll
    for (int o = 0; o < NOUT; o++) {
        #pragma unroll
        for (int sh = 16; sh > 0; sh >>= 1)
            acc[o] += __shfl_down_sync(0xffffffffu, acc[o], sh);
    }
    if (lane == 0) {
        #pragma unroll
        for (int o = 0; o < NOUT; o++) out[warp * NOUT + o] = acc[o] + bias[o];
    }
}

// ---------------- host orchestration ----------------
static inline dim3 gemm_grid(int M, int N) {
    return dim3((N + BN - 1) / BN, (M + BM - 1) / BM);
}

template<typename T> static float* devptr(T& sym) {
    void* p = nullptr;
    cudaGetSymbolAddress(&p, sym);
    return (float*)p;
}

extern "C" void kernel_launch(void* const* d_in, const int* in_sizes, int n_in,
                              void* d_out, int out_size)
{
    const float* x_src    = (const float*)d_in[0];
    const float* y_src    = (const float*)d_in[1];
    const float* enc_w    = (const float*)d_in[2];
    const float* enc_b    = (const float*)d_in[3];
    const float* yenc_w   = (const float*)d_in[4];
    const float* yenc_b   = (const float*)d_in[5];
    const float* norm_w   = (const float*)d_in[6];
    const float* norm_b   = (const float*)d_in[7];
    const float* in_proj_w= (const float*)d_in[8];
    const float* conv_w   = (const float*)d_in[9];
    const float* conv_b   = (const float*)d_in[10];
    const float* x_proj_w = (const float*)d_in[11];
    const float* dt_w     = (const float*)d_in[12];
    const float* dt_b     = (const float*)d_in[13];
    const float* A_log    = (const float*)d_in[14];
    const float* D_ssm    = (const float*)d_in[15];
    const float* out_w    = (const float*)d_in[16];
    const float* normf_w  = (const float*)d_in[17];
    const float* normf_b  = (const float*)d_in[18];
    const float* dec1_w   = (const float*)d_in[19];
    const float* dec1_b   = (const float*)d_in[20];
    const float* dec2_w   = (const float*)d_in[21];
    const float* dec2_b   = (const float*)d_in[22];
    float* out = (float*)d_out;

    float* p_xT   = devptr(g_xT);
    float* p_h    = devptr(g_h);
    float* p_res  = devptr(g_res);
    float* p_hn   = devptr(g_hn);
    float* p_xz   = devptr(g_xz);
    float* p_xc   = devptr(g_xc);
    float* p_xdbl = devptr(g_xdbl);
    float* p_dt   = devptr(g_dt);
    float* p_y    = devptr(g_y);
    float* p_dec  = devptr(g_dec);
    float* p_mid  = devptr(g_mid);

    gather_x_kernel<<<(MROWS*FF + 255)/256, 256>>>(x_src);
    tgemm_tn<0><<<gemm_grid(MROWS, DD), 256>>>(p_xT, enc_w, enc_b, p_h,
                                               MROWS, DD, FF, FF, FF, DD);
    add_yenc_kernel<<<(MROWS*DD + 255)/256, 256>>>(y_src, yenc_w, yenc_b);

    for (int i = 0; i < NLAYER; i++) {
        resln_kernel<<<MROWS, 256>>>(p_h, p_res, p_hn,
                                     norm_w + i*DD, norm_b + i*DD, i == 0);
        tgemm_tn<0><<<gemm_grid(MROWS, 2*DI), 256>>>(
            p_hn, in_proj_w + (size_t)i * (2*DI) * DD, nullptr, p_xz,
            MROWS, 2*DI, DD, DD, DD, 2*DI);
        conv_silu_kernel<<<(MROWS*DI + 255)/256, 256>>>(conv_w + i*DI*KCONV, conv_b + i*DI);
        tgemm_tn<0><<<gemm_grid(MROWS, RR + 2*NST), 256>>>(
            p_xc, x_proj_w + (size_t)i * (RR + 2*NST) * DI, nullptr, p_xdbl,
            MROWS, RR + 2*NST, DI, DI, DI, RR + 2*NST);
        tgemm_tn<1><<<gemm_grid(MROWS, DI), 256>>>(
            p_xdbl, dt_w + (size_t)i * DI * RR, dt_b + i*DI, p_dt,
            MROWS, DI, RR, RR + 2*NST, RR, DI);
        scan_kernel<<<(BB*DI + 255)/256, 256>>>(A_log + (size_t)i * DI * NST, D_ssm + i*DI);
        tgemm_tn<0><<<gemm_grid(MROWS, DD), 256>>>(
            p_y, out_w + (size_t)i * DD * DI, nullptr, p_h,
            MROWS, DD, DI, DI, DI, DD);
    }

    resln_kernel<<<MROWS, 256>>>(p_h, p_res, p_hn, normf_w, normf_b, 0);

    gather_dec_kernel<<<(MDEC*DD + 255)/256, 256>>>();
    tgemm_tn<2><<<gemm_grid(MDEC, HH), 256>>>(p_dec, dec1_w, dec1_b, p_mid,
                                              MDEC, HH, DD, DD, DD, HH);
    dec2_kernel<<<(MDEC*32 + 255)/256, 256>>>(dec2_w, dec2_b, out);
}

// round 3
// speedup vs baseline: 3.7873x; 2.3559x over previous
#include <cuda_runtime.h>
#include <cuda_bf16.h>
#include <math.h>

// ---------------- problem dims (fixed by dataset) ----------------
#define LL     1024
#define BB     4
#define FF     128
#define DD     1024
#define DI     2048
#define NST    16
#define KCONV  4
#define RR     64
#define HH     2048
#define NOUT   10
#define NLAYER 4
#define MROWS  (BB*LL)
#define SEP    512
#define MDEC   ((LL-SEP)*BB)
#define NCH    16
#define CL     (LL/NCH)      // 64 steps per chunk

// ---------------- scratch ----------------
__device__ float g_xT  [MROWS*FF];
__device__ float g_h   [MROWS*DD];
__device__ float g_res [MROWS*DD];
__device__ float g_hn  [MROWS*DD];
__device__ float g_xz  [MROWS*(2*DI)];
__device__ float g_xc  [MROWS*DI];
__device__ float g_xdbl[MROWS*(RR+2*NST)];
__device__ float g_dt  [MROWS*DI];
__device__ float g_y   [MROWS*DI];
__device__ float g_dec [MDEC*DD];
__device__ float g_mid [MDEC*HH];
// scan chunking scratch, layout [c][n][b*DI+d]
__device__ float g_hloc [NCH*NST*BB*DI];
__device__ float g_hin  [NCH*NST*BB*DI];
__device__ float g_sumdt[NCH*BB*DI];

// ---------------- TF32 GEMM with cp.async double buffering ----------------
#define BM 128
#define BN 128
#define BK 16
#define LDSA 20
#define STG_FLOATS (2*BM*LDSA)          // A+B per stage
#define A_BYTES    (BM*LDSA*4)
#define STG_BYTES  (STG_FLOATS*4)

__device__ __forceinline__ unsigned rtf(unsigned raw) {
    unsigned u;
    asm("cvt.rna.tf32.f32 %0, %1;" : "=r"(u) : "f"(__uint_as_float(raw)));
    return u;
}

__device__ __forceinline__ void cp16(unsigned dst, const float* src, bool pred) {
    int sz = pred ? 16 : 0;
    asm volatile("cp.async.cg.shared.global [%0], [%1], 16, %2;"
                 :: "r"(dst), "l"(src), "r"(sz));
}

__device__ __forceinline__ void ldsm_x4(unsigned& d0, unsigned& d1, unsigned& d2, unsigned& d3,
                                        unsigned addr) {
    asm volatile("ldmatrix.sync.aligned.m8n8.x4.shared.b16 {%0,%1,%2,%3}, [%4];"
                 : "=r"(d0), "=r"(d1), "=r"(d2), "=r"(d3) : "r"(addr));
}

__device__ __forceinline__ void mma_tf32(float* c, const unsigned* a, const unsigned* b) {
    asm volatile("mma.sync.aligned.m16n8k8.row.col.f32.tf32.tf32.f32 "
                 "{%0,%1,%2,%3}, {%4,%5,%6,%7}, {%8,%9}, {%0,%1,%2,%3};"
                 : "+f"(c[0]), "+f"(c[1]), "+f"(c[2]), "+f"(c[3])
                 : "r"(a[0]), "r"(a[1]), "r"(a[2]), "r"(a[3]), "r"(b[0]), "r"(b[1]));
}

template<int ACT>   // 0 none, 1 softplus, 2 gelu
__global__ __launch_bounds__(256, 2)
void tgemm_tn(const float* __restrict__ A, const float* __restrict__ B,
              const float* __restrict__ bias, float* __restrict__ C,
              int M, int N, int K, int lda, int ldb, int ldc)
{
    __shared__ __align__(16) float sm[2][STG_FLOATS];

    const int tid  = threadIdx.x;
    const int lane = tid & 31;
    const int warp = tid >> 5;
    const int wm = (warp >> 2) * 64;
    const int wn = (warp & 3) * 32;
    const int rowBase = blockIdx.y * BM;
    const int colBase = blockIdx.x * BN;

    const unsigned sbase = (unsigned)__cvta_generic_to_shared(&sm[0][0]);

    // loader coords: i = tid + ld*256 -> r = i>>2, kc = (i&3)*4
    const int r0  = tid >> 2;
    const int kc0 = (tid & 3) * 4;
    const int r1  = (tid + 256) >> 2;
    const int kc1 = ((tid + 256) & 3) * 4;
    const bool pa0 = (rowBase + r0) < M, pa1 = (rowBase + r1) < M;
    const bool pb0 = (colBase + r0) < N, pb1 = (colBase + r1) < N;
    const float* A0 = A + (size_t)(rowBase + r0) * lda + kc0;
    const float* A1 = A + (size_t)(rowBase + r1) * lda + kc1;
    const float* B0 = B + (size_t)(colBase + r0) * ldb + kc0;
    const float* B1 = B + (size_t)(colBase + r1) * ldb + kc1;
    const unsigned dA0 = (r0 * LDSA + kc0) * 4;
    const unsigned dA1 = (r1 * LDSA + kc1) * 4;
    const unsigned dB0 = A_BYTES + dA0;
    const unsigned dB1 = A_BYTES + dA1;

    float acc[4][4][4];
    #pragma unroll
    for (int mi = 0; mi < 4; mi++)
        #pragma unroll
        for (int ni = 0; ni < 4; ni++)
            #pragma unroll
            for (int e = 0; e < 4; e++) acc[mi][ni][e] = 0.f;

    // ldmatrix per-lane address components
    const int jr = lane >> 3;
    const int r8 = lane & 7;
    const int a_row = wm + ((jr & 1) << 3) + r8;
    const int a_col = (jr >> 1) << 2;
    const int b_row = wn + ((jr >> 1) << 3) + r8;
    const int b_col = (jr & 1) << 2;

    const int ktiles = K / BK;

    // prologue: stage 0
    {
        cp16(sbase + dA0, A0, pa0);
        cp16(sbase + dA1, A1, pa1);
        cp16(sbase + dB0, B0, pb0);
        cp16(sbase + dB1, B1, pb1);
        asm volatile("cp.async.commit_group;");
    }

    for (int kt = 0; kt < ktiles; ++kt) {
        asm volatile("cp.async.wait_group 0;");
        __syncthreads();

        const unsigned stgC = (kt & 1) ? STG_BYTES : 0;
        if (kt + 1 < ktiles) {
            const unsigned stgN = ((kt + 1) & 1) ? STG_BYTES : 0;
            const int ko = (kt + 1) * BK;
            cp16(sbase + stgN + dA0, A0 + ko, pa0);
            cp16(sbase + stgN + dA1, A1 + ko, pa1);
            cp16(sbase + stgN + dB0, B0 + ko, pb0);
            cp16(sbase + stgN + dB1, B1 + ko, pb1);
            asm volatile("cp.async.commit_group;");
        }

        const unsigned sA = sbase + stgC;
        const unsigned sB = sbase + stgC + A_BYTES;

        #pragma unroll
        for (int ks = 0; ks < 2; ks++) {
            const int k0 = ks * 8;
            unsigned afr[4][4];
            #pragma unroll
            for (int mi = 0; mi < 4; mi++) {
                unsigned addr = sA + ((a_row + mi * 16) * LDSA + k0 + a_col) * 4;
                ldsm_x4(afr[mi][0], afr[mi][1], afr[mi][2], afr[mi][3], addr);
                afr[mi][0] = rtf(afr[mi][0]); afr[mi][1] = rtf(afr[mi][1]);
                afr[mi][2] = rtf(afr[mi][2]); afr[mi][3] = rtf(afr[mi][3]);
            }
            unsigned bfr[4][2];
            #pragma unroll
            for (int np = 0; np < 2; np++) {
                unsigned addr = sB + ((b_row + np * 16) * LDSA + k0 + b_col) * 4;
                ldsm_x4(bfr[np*2][0], bfr[np*2][1], bfr[np*2+1][0], bfr[np*2+1][1], addr);
                bfr[np*2][0]   = rtf(bfr[np*2][0]);   bfr[np*2][1]   = rtf(bfr[np*2][1]);
                bfr[np*2+1][0] = rtf(bfr[np*2+1][0]); bfr[np*2+1][1] = rtf(bfr[np*2+1][1]);
            }
            #pragma unroll
            for (int mi = 0; mi < 4; mi++)
                #pragma unroll
                for (int ni = 0; ni < 4; ni++)
                    mma_tf32(acc[mi][ni], afr[mi], bfr[ni]);
        }
        __syncthreads();
    }

    // epilogue (float2 stores)
    const int rg = lane >> 2;
    const int cg = (lane & 3) * 2;
    #pragma unroll
    for (int mi = 0; mi < 4; mi++) {
        #pragma unroll
        for (int ni = 0; ni < 4; ni++) {
            #pragma unroll
            for (int eh = 0; eh < 2; eh++) {    // e pairs (0,1),(2,3)
                int r = rowBase + wm + mi * 16 + rg + eh * 8;
                int c = colBase + wn + ni * 8 + cg;
                if (r >= M || c + 1 >= N + 1) continue;
                if (c >= N) continue;
                float v0 = acc[mi][ni][eh*2+0];
                float v1 = acc[mi][ni][eh*2+1];
                if (bias) { v0 += bias[c]; v1 += bias[c+1]; }
                if (ACT == 1) {
                    v0 = fmaxf(v0, 0.f) + log1pf(__expf(-fabsf(v0)));
                    v1 = fmaxf(v1, 0.f) + log1pf(__expf(-fabsf(v1)));
                } else if (ACT == 2) {
                    v0 = 0.5f * v0 * (1.f + erff(v0 * 0.70710678118654752f));
                    v1 = 0.5f * v1 * (1.f + erff(v1 * 0.70710678118654752f));
                }
                if (c + 1 < N) {
                    *reinterpret_cast<float2*>(C + (size_t)r * ldc + c) = make_float2(v0, v1);
                } else {
                    C[(size_t)r * ldc + c] = v0;
                }
            }
        }
    }
}

// ---------------- elementwise / helper kernels ----------------

__global__ void gather_x_kernel(const float* __restrict__ x_src)
{
    int idx = blockIdx.x * blockDim.x + threadIdx.x;
    if (idx >= MROWS * FF) return;
    int t = idx >> 7, f = idx & 127;
    int b = t >> 10, l = t & 1023;
    g_xT[idx] = x_src[(l * BB + b) * FF + f];
}

__global__ void add_yenc_kernel(const float* __restrict__ y_src,
                                const float* __restrict__ yenc_w,
                                const float* __restrict__ yenc_b)
{
    int idx = blockIdx.x * blockDim.x + threadIdx.x;
    if (idx >= MROWS * DD) return;
    int t = idx >> 10, d = idx & 1023;
    int b = t >> 10, l = t & 1023;
    if (l < SEP)
        g_h[idx] += y_src[l * BB + b] * yenc_w[d] + yenc_b[d];
}

__global__ __launch_bounds__(256)
void resln_kernel(const float* __restrict__ h, float* __restrict__ res,
                  float* __restrict__ out, const float* __restrict__ w,
                  const float* __restrict__ bb, int first)
{
    __shared__ float sbuf[256];
    int row = blockIdx.x;
    int tid = threadIdx.x;
    float v[4];
    float s = 0.f;
    #pragma unroll
    for (int j = 0; j < 4; j++) {
        int c = tid + j * 256;
        size_t idx = (size_t)row * DD + c;
        float x = h[idx];
        if (!first) x += res[idx];
        res[idx] = x;
        v[j] = x;
        s += x;
    }
    sbuf[tid] = s; __syncthreads();
    for (int st = 128; st > 0; st >>= 1) { if (tid < st) sbuf[tid] += sbuf[tid + st]; __syncthreads(); }
    float mean = sbuf[0] * (1.f / DD);
    __syncthreads();
    float s2 = 0.f;
    #pragma unroll
    for (int j = 0; j < 4; j++) { float dv = v[j] - mean; s2 += dv * dv; }
    sbuf[tid] = s2; __syncthreads();
    for (int st = 128; st > 0; st >>= 1) { if (tid < st) sbuf[tid] += sbuf[tid + st]; __syncthreads(); }
    float rstd = rsqrtf(sbuf[0] * (1.f / DD) + 1e-5f);
    #pragma unroll
    for (int j = 0; j < 4; j++) {
        int c = tid + j * 256;
        out[(size_t)row * DD + c] = (v[j] - mean) * rstd * w[c] + bb[c];
    }
}

__global__ void conv_silu_kernel(const float* __restrict__ cw, const float* __restrict__ cb)
{
    int idx = blockIdx.x * blockDim.x + threadIdx.x;
    if (idx >= MROWS * DI) return;
    int d = idx & (DI - 1);
    int t = idx >> 11;
    int b = t >> 10, l = t & 1023;
    const float* base = g_xz + (size_t)(b << 10) * (2 * DI) + d;
    float w0 = cw[d*4+0], w1 = cw[d*4+1], w2 = cw[d*4+2], w3 = cw[d*4+3];
    float v = cb[d];
    v += w3 * base[(size_t)l * (2*DI)];
    if (l >= 1) v += w2 * base[(size_t)(l-1) * (2*DI)];
    if (l >= 2) v += w1 * base[(size_t)(l-2) * (2*DI)];
    if (l >= 3) v += w0 * base[(size_t)(l-3) * (2*DI)];
    g_xc[idx] = v / (1.f + __expf(-v));
}

// ---- chunked scan: pass 1 (local scans from zero state) ----
__global__ __launch_bounds__(256)
void scan_local_kernel(const float* __restrict__ A_log)
{
    int gid = blockIdx.x * blockDim.x + threadIdx.x;     // BB*DI*NCH
    if (gid >= BB * DI * NCH) return;
    int d = gid & (DI - 1);
    int rest = gid >> 11;
    int b = rest & (BB - 1);
    int c = rest >> 2;

    float Ac[NST], hs[NST];
    #pragma unroll
    for (int n = 0; n < NST; n++) {
        Ac[n] = -__expf(A_log[d * NST + n]);
        hs[n] = 0.f;
    }
    float sdt = 0.f;

    const int lbeg = c * CL;
    for (int l = lbeg; l < lbeg + CL; l++) {
        int t = (b << 10) + l;
        float dtv = g_dt[(size_t)t * DI + d];
        float xv  = g_xc[(size_t)t * DI + d];
        const float* bc = g_xdbl + (size_t)t * (RR + 2*NST) + RR;
        sdt += dtv;
        float dtx = dtv * xv;
        #pragma unroll
        for (int n = 0; n < NST; n++)
            hs[n] = hs[n] * __expf(dtv * Ac[n]) + dtx * bc[n];
    }
    int bd = (b << 11) + d;
    #pragma unroll
    for (int n = 0; n < NST; n++)
        g_hloc[((size_t)(c * NST + n)) * (BB*DI) + bd] = hs[n];
    g_sumdt[(size_t)c * (BB*DI) + bd] = sdt;
}

// ---- chunked scan: pass 2 (combine chunk transitions) ----
__global__ __launch_bounds__(256)
void scan_combine_kernel(const float* __restrict__ A_log)
{
    int gid = blockIdx.x * blockDim.x + threadIdx.x;     // BB*DI
    if (gid >= BB * DI) return;
    int d = gid & (DI - 1);
    int bd = gid;

    float Ac[NST], h[NST];
    #pragma unroll
    for (int n = 0; n < NST; n++) {
        Ac[n] = -__expf(A_log[d * NST + n]);
        h[n] = 0.f;
    }
    for (int c = 0; c < NCH; c++) {
        #pragma unroll
        for (int n = 0; n < NST; n++)
            g_hin[((size_t)(c * NST + n)) * (BB*DI) + bd] = h[n];
        float sdt = g_sumdt[(size_t)c * (BB*DI) + bd];
        #pragma unroll
        for (int n = 0; n < NST; n++) {
            float P = __expf(Ac[n] * sdt);
            h[n] = h[n] * P + g_hloc[((size_t)(c * NST + n)) * (BB*DI) + bd];
        }
    }
}

// ---- chunked scan: pass 3 (replay with entry state + fused epilogue) ----
__global__ __launch_bounds__(256)
void scan_final_kernel(const float* __restrict__ A_log, const float* __restrict__ Dss)
{
    int gid = blockIdx.x * blockDim.x + threadIdx.x;     // BB*DI*NCH
    if (gid >= BB * DI * NCH) return;
    int d = gid & (DI - 1);
    int rest = gid >> 11;
    int b = rest & (BB - 1);
    int c = rest >> 2;
    int bd = (b << 11) + d;

    float Ac[NST], hs[NST];
    #pragma unroll
    for (int n = 0; n < NST; n++) {
        Ac[n] = -__expf(A_log[d * NST + n]);
        hs[n] = g_hin[((size_t)(c * NST + n)) * (BB*DI) + bd];
    }
    float Dd = Dss[d];

    const int lbeg = c * CL;
    for (int l = lbeg; l < lbeg + CL; l++) {
        int t = (b << 10) + l;
        float dtv = g_dt[(size_t)t * DI + d];
        float xv  = g_xc[(size_t)t * DI + d];
        const float* bc = g_xdbl + (size_t)t * (RR + 2*NST) + RR;
        float dtx = dtv * xv;
        float accv = 0.f;
        #pragma unroll
        for (int n = 0; n < NST; n++) {
            hs[n] = hs[n] * __expf(dtv * Ac[n]) + dtx * bc[n];
            accv += hs[n] * bc[NST + n];
        }
        float zv = g_xz[(size_t)t * (2*DI) + DI + d];
        float gate = zv / (1.f + __expf(-zv));
        g_y[(size_t)t * DI + d] = (accv + Dd * xv) * gate;
    }
}

__global__ void gather_dec_kernel()
{
    int idx = blockIdx.x * blockDim.x + threadIdx.x;
    if (idx >= MDEC * DD) return;
    int r = idx >> 10, d = idx & 1023;
    int b = r & 3;
    int l = SEP + (r >> 2);
    g_dec[idx] = g_hn[((size_t)b * LL + l) * DD + d];
}

__global__ __launch_bounds__(256)
void dec2_kernel(const float* __restrict__ w, const float* __restrict__ bias,
                 float* __restrict__ out)
{
    int warp = (blockIdx.x * blockDim.x + threadIdx.x) >> 5;
    int lane = threadIdx.x & 31;
    if (warp >= MDEC) return;
    float acc[NOUT];
    #pragma unroll
    for (int o = 0; o < NOUT; o++) acc[o] = 0.f;
    const float* a = g_mid + (size_t)warp * HH;
    for (int k = lane; k < HH; k += 32) {
        float av = a[k];
        #pragma unroll
        for (int o = 0; o < NOUT; o++) acc[o] += av * w[o * HH + k];
    }
    #pragma unroll
    for (int o = 0; o < NOUT; o++) {
        #pragma unroll
        for (int sh = 16; sh > 0; sh >>= 1)
            acc[o] += __shfl_down_sync(0xffffffffu, acc[o], sh);
    }
    if (lane == 0) {
        #pragma unroll
        for (int o = 0; o < NOUT; o++) out[warp * NOUT + o] = acc[o] + bias[o];
    }
}

// ---------------- host orchestration ----------------
static inline dim3 gemm_grid(int M, int N) {
    return dim3((N + BN - 1) / BN, (M + BM - 1) / BM);
}

template<typename T> static float* devptr(T& sym) {
    void* p = nullptr;
    cudaGetSymbolAddress(&p, sym);
    return (float*)p;
}

extern "C" void kernel_launch(void* const* d_in, const int* in_sizes, int n_in,
                              void* d_out, int out_size)
{
    const float* x_src    = (const float*)d_in[0];
    const float* y_src    = (const float*)d_in[1];
    const float* enc_w    = (const float*)d_in[2];
    const float* enc_b    = (const float*)d_in[3];
    const float* yenc_w   = (const float*)d_in[4];
    const float* yenc_b   = (const float*)d_in[5];
    const float* norm_w   = (const float*)d_in[6];
    const float* norm_b   = (const float*)d_in[7];
    const float* in_proj_w= (const float*)d_in[8];
    const float* conv_w   = (const float*)d_in[9];
    const float* conv_b   = (const float*)d_in[10];
    const float* x_proj_w = (const float*)d_in[11];
    const float* dt_w     = (const float*)d_in[12];
    const float* dt_b     = (const float*)d_in[13];
    const float* A_log    = (const float*)d_in[14];
    const float* D_ssm    = (const float*)d_in[15];
    const float* out_w    = (const float*)d_in[16];
    const float* normf_w  = (const float*)d_in[17];
    const float* normf_b  = (const float*)d_in[18];
    const float* dec1_w   = (const float*)d_in[19];
    const float* dec1_b   = (const float*)d_in[20];
    const float* dec2_w   = (const float*)d_in[21];
    const float* dec2_b   = (const float*)d_in[22];
    float* out = (float*)d_out;

    float* p_xT   = devptr(g_xT);
    float* p_h    = devptr(g_h);
    float* p_res  = devptr(g_res);
    float* p_hn   = devptr(g_hn);
    float* p_xz   = devptr(g_xz);
    float* p_xc   = devptr(g_xc);
    float* p_xdbl = devptr(g_xdbl);
    float* p_dt   = devptr(g_dt);
    float* p_y    = devptr(g_y);
    float* p_dec  = devptr(g_dec);
    float* p_mid  = devptr(g_mid);

    gather_x_kernel<<<(MROWS*FF + 255)/256, 256>>>(x_src);
    tgemm_tn<0><<<gemm_grid(MROWS, DD), 256>>>(p_xT, enc_w, enc_b, p_h,
                                               MROWS, DD, FF, FF, FF, DD);
    add_yenc_kernel<<<(MROWS*DD + 255)/256, 256>>>(y_src, yenc_w, yenc_b);

    for (int i = 0; i < NLAYER; i++) {
        resln_kernel<<<MROWS, 256>>>(p_h, p_res, p_hn,
                                     norm_w + i*DD, norm_b + i*DD, i == 0);
        tgemm_tn<0><<<gemm_grid(MROWS, 2*DI), 256>>>(
            p_hn, in_proj_w + (size_t)i * (2*DI) * DD, nullptr, p_xz,
            MROWS, 2*DI, DD, DD, DD, 2*DI);
        conv_silu_kernel<<<(MROWS*DI + 255)/256, 256>>>(conv_w + i*DI*KCONV, conv_b + i*DI);
        tgemm_tn<0><<<gemm_grid(MROWS, RR + 2*NST), 256>>>(
            p_xc, x_proj_w + (size_t)i * (RR + 2*NST) * DI, nullptr, p_xdbl,
            MROWS, RR + 2*NST, DI, DI, DI, RR + 2*NST);
        tgemm_tn<1><<<gemm_grid(MROWS, DI), 256>>>(
            p_xdbl, dt_w + (size_t)i * DI * RR, dt_b + i*DI, p_dt,
            MROWS, DI, RR, RR + 2*NST, RR, DI);
        scan_local_kernel  <<<(BB*DI*NCH + 255)/256, 256>>>(A_log + (size_t)i * DI * NST);
        scan_combine_kernel<<<(BB*DI     + 255)/256, 256>>>(A_log + (size_t)i * DI * NST);
        scan_final_kernel  <<<(BB*DI*NCH + 255)/256, 256>>>(A_log + (size_t)i * DI * NST,
                                                            D_ssm + i*DI);
        tgemm_tn<0><<<gemm_grid(MROWS, DD), 256>>>(
            p_y, out_w + (size_t)i * DD * DI, nullptr, p_h,
            MROWS, DD, DI, DI, DI, DD);
    }

    resln_kernel<<<MROWS, 256>>>(p_h, p_res, p_hn, normf_w, normf_b, 0);

    gather_dec_kernel<<<(MDEC*DD + 255)/256, 256>>>();
    tgemm_tn<2><<<gemm_grid(MDEC, HH), 256>>>(p_dec, dec1_w, dec1_b, p_mid,
                                              MDEC, HH, DD, DD, DD, HH);
    dec2_kernel<<<(MDEC*32 + 255)/256, 256>>>(dec2_w, dec2_b, out);
}

// round 6
// speedup vs baseline: 4.3952x; 1.1605x over previous
#include <cuda_runtime.h>
#include <cuda_bf16.h>
#include <math.h>

// ---------------- problem dims ----------------
#define LL     1024
#define BB     4
#define FF     128
#define DD     1024
#define DI     2048
#define NST    16
#define KCONV  4
#define RR     64
#define HH     2048
#define NOUT   10
#define NLAYER 4
#define MROWS  (BB*LL)
#define SEP    512
#define MDEC   ((LL-SEP)*BB)
#define NCH    16
#define CL     (LL/NCH)
#define XP     (RR+2*NST)    // 96
#define KSPLIT 4

// ---------------- scratch ----------------
__device__ float g_xT  [MROWS*FF];
__device__ float g_h   [MROWS*DD];
__device__ float g_res [MROWS*DD];
__device__ float g_hn  [MROWS*DD];
__device__ float g_xz  [MROWS*(2*DI)];
__device__ float g_xc  [MROWS*DI];       // exact (scan)
__device__ float g_xcr [MROWS*DI];       // tf32-rounded (x_proj A)
__device__ float g_xdbl[MROWS*XP];
__device__ float g_xpart[KSPLIT*MROWS*XP];
__device__ float g_dt  [MROWS*DI];
__device__ float g_y   [MROWS*DI];
__device__ float g_dec [MDEC*DD];
__device__ float g_mid [MDEC*HH];
__device__ float g_hloc [NCH*NST*BB*DI];
__device__ float g_hin  [NCH*NST*BB*DI];
__device__ float g_sumdt[NCH*BB*DI];
// tf32-rounded weights
__device__ float w_enc [DD*FF];
__device__ float w_inp [NLAYER*2*DI*DD];
__device__ float w_xp  [NLAYER*XP*DI];
__device__ float w_dtw [NLAYER*DI*RR];
__device__ float w_outw[NLAYER*DD*DI];
__device__ float w_dec1[HH*DD];

// ---------------- helpers ----------------
__device__ __forceinline__ float rtf32f(float f) {
    unsigned u;
    asm("cvt.rna.tf32.f32 %0, %1;" : "=r"(u) : "f"(f));
    return __uint_as_float(u);
}

__global__ void round4_kernel(const float4* __restrict__ src, float4* __restrict__ dst, int n4)
{
    int i = blockIdx.x * blockDim.x + threadIdx.x;
    if (i >= n4) return;
    float4 v = src[i];
    v.x = rtf32f(v.x); v.y = rtf32f(v.y); v.z = rtf32f(v.z); v.w = rtf32f(v.w);
    dst[i] = v;
}

// ---------------- TF32 GEMM: 2-stage cp.async (static smem), no in-loop cvt ----------------
#define BM 128
#define BN 128
#define BK 16
#define LDSA 20
#define STG_FLOATS (2*BM*LDSA)
#define A_BYTES    (BM*LDSA*4)
#define STG_BYTES  (STG_FLOATS*4)

__device__ __forceinline__ void cp16(unsigned dst, const float* src, bool pred) {
    int sz = pred ? 16 : 0;
    asm volatile("cp.async.cg.shared.global [%0], [%1], 16, %2;"
                 :: "r"(dst), "l"(src), "r"(sz));
}
__device__ __forceinline__ void ldsm_x4(unsigned& d0, unsigned& d1, unsigned& d2, unsigned& d3,
                                        unsigned addr) {
    asm volatile("ldmatrix.sync.aligned.m8n8.x4.shared.b16 {%0,%1,%2,%3}, [%4];"
                 : "=r"(d0), "=r"(d1), "=r"(d2), "=r"(d3) : "r"(addr));
}
__device__ __forceinline__ void mma_tf32(float* c, const unsigned* a, const unsigned* b) {
    asm volatile("mma.sync.aligned.m16n8k8.row.col.f32.tf32.tf32.f32 "
                 "{%0,%1,%2,%3}, {%4,%5,%6,%7}, {%8,%9}, {%0,%1,%2,%3};"
                 : "+f"(c[0]), "+f"(c[1]), "+f"(c[2]), "+f"(c[3])
                 : "r"(a[0]), "r"(a[1]), "r"(a[2]), "r"(a[3]), "r"(b[0]), "r"(b[1]));
}

template<int ACT>   // 0 none, 1 softplus, 2 gelu
__global__ __launch_bounds__(256, 2)
void tgemm_tn(const float* __restrict__ A, const float* __restrict__ B,
              const float* __restrict__ bias, float* __restrict__ C,
              int M, int N, int K, int lda, int ldb, int ldc, size_t zCstride)
{
    __shared__ __align__(16) float sm[2][STG_FLOATS];

    // split-K via blockIdx.z: K is the per-split depth
    const int kz = blockIdx.z;
    A += (size_t)kz * K;
    B += (size_t)kz * K;
    C += (size_t)kz * zCstride;

    const int tid  = threadIdx.x;
    const int lane = tid & 31;
    const int warp = tid >> 5;
    const int wm = (warp >> 2) * 64;
    const int wn = (warp & 3) * 32;
    const int rowBase = blockIdx.y * BM;
    const int colBase = blockIdx.x * BN;

    const unsigned sbase = (unsigned)__cvta_generic_to_shared(&sm[0][0]);

    const int r0  = tid >> 2;
    const int kc0 = (tid & 3) * 4;
    const int r1  = (tid + 256) >> 2;
    const int kc1 = ((tid + 256) & 3) * 4;
    const bool pa0 = (rowBase + r0) < M, pa1 = (rowBase + r1) < M;
    const bool pb0 = (colBase + r0) < N, pb1 = (colBase + r1) < N;
    const float* A0 = A + (size_t)(rowBase + r0) * lda + kc0;
    const float* A1 = A + (size_t)(rowBase + r1) * lda + kc1;
    const float* B0 = B + (size_t)(colBase + r0) * ldb + kc0;
    const float* B1 = B + (size_t)(colBase + r1) * ldb + kc1;
    const unsigned dA0 = (r0 * LDSA + kc0) * 4;
    const unsigned dA1 = (r1 * LDSA + kc1) * 4;
    const unsigned dB0 = A_BYTES + dA0;
    const unsigned dB1 = A_BYTES + dA1;

    float acc[4][4][4];
    #pragma unroll
    for (int mi = 0; mi < 4; mi++)
        #pragma unroll
        for (int ni = 0; ni < 4; ni++)
            #pragma unroll
            for (int e = 0; e < 4; e++) acc[mi][ni][e] = 0.f;

    const int jr = lane >> 3;
    const int r8 = lane & 7;
    const int a_row = wm + ((jr & 1) << 3) + r8;
    const int a_col = (jr >> 1) << 2;
    const int b_row = wn + ((jr >> 1) << 3) + r8;
    const int b_col = (jr & 1) << 2;

    const int ktiles = K / BK;

    // prologue: stage 0
    {
        cp16(sbase + dA0, A0, pa0);
        cp16(sbase + dA1, A1, pa1);
        cp16(sbase + dB0, B0, pb0);
        cp16(sbase + dB1, B1, pb1);
        asm volatile("cp.async.commit_group;");
    }

    for (int kt = 0; kt < ktiles; ++kt) {
        asm volatile("cp.async.wait_group 0;");
        __syncthreads();

        // issue next stage
        if (kt + 1 < ktiles) {
            const unsigned off = ((kt + 1) & 1) ? STG_BYTES : 0;
            const int ko = (kt + 1) * BK;
            cp16(sbase + off + dA0, A0 + ko, pa0);
            cp16(sbase + off + dA1, A1 + ko, pa1);
            cp16(sbase + off + dB0, B0 + ko, pb0);
            cp16(sbase + off + dB1, B1 + ko, pb1);
            asm volatile("cp.async.commit_group;");
        } else {
            asm volatile("cp.async.commit_group;");
        }

        const unsigned stgC = (kt & 1) ? STG_BYTES : 0;
        const unsigned sA = sbase + stgC;
        const unsigned sB = sbase + stgC + A_BYTES;

        #pragma unroll
        for (int ks = 0; ks < 2; ks++) {
            const int k0 = ks * 8;
            unsigned afr[4][4];
            #pragma unroll
            for (int mi = 0; mi < 4; mi++) {
                unsigned addr = sA + ((a_row + mi * 16) * LDSA + k0 + a_col) * 4;
                ldsm_x4(afr[mi][0], afr[mi][1], afr[mi][2], afr[mi][3], addr);
            }
            unsigned bfr[4][2];
            #pragma unroll
            for (int np = 0; np < 2; np++) {
                unsigned addr = sB + ((b_row + np * 16) * LDSA + k0 + b_col) * 4;
                ldsm_x4(bfr[np*2][0], bfr[np*2][1], bfr[np*2+1][0], bfr[np*2+1][1], addr);
            }
            #pragma unroll
            for (int mi = 0; mi < 4; mi++)
                #pragma unroll
                for (int ni = 0; ni < 4; ni++)
                    mma_tf32(acc[mi][ni], afr[mi], bfr[ni]);
        }
        __syncthreads();
    }

    // epilogue
    const int rg = lane >> 2;
    const int cg = (lane & 3) * 2;
    #pragma unroll
    for (int mi = 0; mi < 4; mi++) {
        #pragma unroll
        for (int ni = 0; ni < 4; ni++) {
            #pragma unroll
            for (int eh = 0; eh < 2; eh++) {
                int r = rowBase + wm + mi * 16 + rg + eh * 8;
                int c = colBase + wn + ni * 8 + cg;
                if (r >= M || c >= N) continue;
                bool has1 = (c + 1 < N);
                float v0 = acc[mi][ni][eh*2+0];
                float v1 = acc[mi][ni][eh*2+1];
                if (bias) { v0 += bias[c]; if (has1) v1 += bias[c+1]; }
                if (ACT == 1) {
                    v0 = fmaxf(v0, 0.f) + log1pf(__expf(-fabsf(v0)));
                    v1 = fmaxf(v1, 0.f) + log1pf(__expf(-fabsf(v1)));
                } else if (ACT == 2) {
                    v0 = 0.5f * v0 * (1.f + erff(v0 * 0.70710678118654752f));
                    v1 = 0.5f * v1 * (1.f + erff(v1 * 0.70710678118654752f));
                }
                if (has1) {
                    *reinterpret_cast<float2*>(C + (size_t)r * ldc + c) = make_float2(v0, v1);
                } else {
                    C[(size_t)r * ldc + c] = v0;
                }
            }
        }
    }
}

// ---------------- elementwise / helper kernels ----------------

__global__ void gather_x_kernel(const float* __restrict__ x_src)
{
    int idx = blockIdx.x * blockDim.x + threadIdx.x;
    if (idx >= MROWS * FF) return;
    int t = idx >> 7, f = idx & 127;
    int b = t >> 10, l = t & 1023;
    g_xT[idx] = rtf32f(x_src[(l * BB + b) * FF + f]);
}

__global__ void add_yenc_kernel(const float* __restrict__ y_src,
                                const float* __restrict__ yenc_w,
                                const float* __restrict__ yenc_b)
{
    int idx = blockIdx.x * blockDim.x + threadIdx.x;
    if (idx >= MROWS * DD) return;
    int t = idx >> 10, d = idx & 1023;
    int b = t >> 10, l = t & 1023;
    if (l < SEP)
        g_h[idx] += y_src[l * BB + b] * yenc_w[d] + yenc_b[d];
}

__global__ __launch_bounds__(256)
void resln_kernel(const float* __restrict__ h, float* __restrict__ res,
                  float* __restrict__ out, const float* __restrict__ w,
                  const float* __restrict__ bb, int first)
{
    __shared__ float sbuf[256];
    int row = blockIdx.x;
    int tid = threadIdx.x;
    float v[4];
    float s = 0.f;
    #pragma unroll
    for (int j = 0; j < 4; j++) {
        int c = tid + j * 256;
        size_t idx = (size_t)row * DD + c;
        float x = h[idx];
        if (!first) x += res[idx];
        res[idx] = x;
        v[j] = x;
        s += x;
    }
    sbuf[tid] = s; __syncthreads();
    for (int st = 128; st > 0; st >>= 1) { if (tid < st) sbuf[tid] += sbuf[tid + st]; __syncthreads(); }
    float mean = sbuf[0] * (1.f / DD);
    __syncthreads();
    float s2 = 0.f;
    #pragma unroll
    for (int j = 0; j < 4; j++) { float dv = v[j] - mean; s2 += dv * dv; }
    sbuf[tid] = s2; __syncthreads();
    for (int st = 128; st > 0; st >>= 1) { if (tid < st) sbuf[tid] += sbuf[tid + st]; __syncthreads(); }
    float rstd = rsqrtf(sbuf[0] * (1.f / DD) + 1e-5f);
    #pragma unroll
    for (int j = 0; j < 4; j++) {
        int c = tid + j * 256;
        out[(size_t)row * DD + c] = rtf32f((v[j] - mean) * rstd * w[c] + bb[c]);
    }
}

__global__ void conv_silu_kernel(const float* __restrict__ cw, const float* __restrict__ cb)
{
    int idx = blockIdx.x * blockDim.x + threadIdx.x;
    if (idx >= MROWS * DI) return;
    int d = idx & (DI - 1);
    int t = idx >> 11;
    int b = t >> 10, l = t & 1023;
    const float* base = g_xz + (size_t)(b << 10) * (2 * DI) + d;
    float w0 = cw[d*4+0], w1 = cw[d*4+1], w2 = cw[d*4+2], w3 = cw[d*4+3];
    float v = cb[d];
    v += w3 * base[(size_t)l * (2*DI)];
    if (l >= 1) v += w2 * base[(size_t)(l-1) * (2*DI)];
    if (l >= 2) v += w1 * base[(size_t)(l-2) * (2*DI)];
    if (l >= 3) v += w0 * base[(size_t)(l-3) * (2*DI)];
    float sv = v / (1.f + __expf(-v));
    g_xc[idx]  = sv;
    g_xcr[idx] = rtf32f(sv);
}

// sum split-K partials; round dt-columns (<RR) for the following GEMM
__global__ void xproj_reduce_kernel()
{
    int idx = blockIdx.x * blockDim.x + threadIdx.x;
    if (idx >= MROWS * XP) return;
    float s = g_xpart[idx] + g_xpart[MROWS*XP + idx]
            + g_xpart[2*MROWS*XP + idx] + g_xpart[3*MROWS*XP + idx];
    int c = idx % XP;
    g_xdbl[idx] = (c < RR) ? rtf32f(s) : s;
}

// ---- chunked scan ----
__global__ __launch_bounds__(256)
void scan_local_kernel(const float* __restrict__ A_log)
{
    int gid = blockIdx.x * blockDim.x + threadIdx.x;
    if (gid >= BB * DI * NCH) return;
    int d = gid & (DI - 1);
    int rest = gid >> 11;
    int b = rest & (BB - 1);
    int c = rest >> 2;

    float Ac[NST], hs[NST];
    #pragma unroll
    for (int n = 0; n < NST; n++) {
        Ac[n] = -__expf(A_log[d * NST + n]);
        hs[n] = 0.f;
    }
    float sdt = 0.f;

    const int lbeg = c * CL;
    for (int l = lbeg; l < lbeg + CL; l++) {
        int t = (b << 10) + l;
        float dtv = g_dt[(size_t)t * DI + d];
        float xv  = g_xc[(size_t)t * DI + d];
        const float* bc = g_xdbl + (size_t)t * XP + RR;
        sdt += dtv;
        float dtx = dtv * xv;
        #pragma unroll
        for (int n = 0; n < NST; n++)
            hs[n] = hs[n] * __expf(dtv * Ac[n]) + dtx * bc[n];
    }
    int bd = (b << 11) + d;
    #pragma unroll
    for (int n = 0; n < NST; n++)
        g_hloc[((size_t)(c * NST + n)) * (BB*DI) + bd] = hs[n];
    g_sumdt[(size_t)c * (BB*DI) + bd] = sdt;
}

__global__ __launch_bounds__(256)
void scan_combine_kernel(const float* __restrict__ A_log)
{
    int gid = blockIdx.x * blockDim.x + threadIdx.x;
    if (gid >= BB * DI) return;
    int d = gid & (DI - 1);
    int bd = gid;

    float Ac[NST], h[NST];
    #pragma unroll
    for (int n = 0; n < NST; n++) {
        Ac[n] = -__expf(A_log[d * NST + n]);
        h[n] = 0.f;
    }
    for (int c = 0; c < NCH; c++) {
        #pragma unroll
        for (int n = 0; n < NST; n++)
            g_hin[((size_t)(c * NST + n)) * (BB*DI) + bd] = h[n];
        float sdt = g_sumdt[(size_t)c * (BB*DI) + bd];
        #pragma unroll
        for (int n = 0; n < NST; n++) {
            float P = __expf(Ac[n] * sdt);
            h[n] = h[n] * P + g_hloc[((size_t)(c * NST + n)) * (BB*DI) + bd];
        }
    }
}

__global__ __launch_bounds__(256)
void scan_final_kernel(const float* __restrict__ A_log, const float* __restrict__ Dss)
{
    int gid = blockIdx.x * blockDim.x + threadIdx.x;
    if (gid >= BB * DI * NCH) return;
    int d = gid & (DI - 1);
    int rest = gid >> 11;
    int b = rest & (BB - 1);
    int c = rest >> 2;
    int bd = (b << 11) + d;

    float Ac[NST], hs[NST];
    #pragma unroll
    for (int n = 0; n < NST; n++) {
        Ac[n] = -__expf(A_log[d * NST + n]);
        hs[n] = g_hin[((size_t)(c * NST + n)) * (BB*DI) + bd];
    }
    float Dd = Dss[d];

    const int lbeg = c * CL;
    for (int l = lbeg; l < lbeg + CL; l++) {
        int t = (b << 10) + l;
        float dtv = g_dt[(size_t)t * DI + d];
        float xv  = g_xc[(size_t)t * DI + d];
        const float* bc = g_xdbl + (size_t)t * XP + RR;
        float dtx = dtv * xv;
        float accv = 0.f;
        #pragma unroll
        for (int n = 0; n < NST; n++) {
            hs[n] = hs[n] * __expf(dtv * Ac[n]) + dtx * bc[n];
            accv += hs[n] * bc[NST + n];
        }
        float zv = g_xz[(size_t)t * (2*DI) + DI + d];
        float gate = zv / (1.f + __expf(-zv));
        g_y[(size_t)t * DI + d] = rtf32f((accv + Dd * xv) * gate);
    }
}

__global__ void gather_dec_kernel()
{
    int idx = blockIdx.x * blockDim.x + threadIdx.x;
    if (idx >= MDEC * DD) return;
    int r = idx >> 10, d = idx & 1023;
    int b = r & 3;
    int l = SEP + (r >> 2);
    g_dec[idx] = g_hn[((size_t)b * LL + l) * DD + d];   // g_hn already tf32-rounded
}

__global__ __launch_bounds__(256)
void dec2_kernel(const float* __restrict__ w, const float* __restrict__ bias,
                 float* __restrict__ out)
{
    int warp = (blockIdx.x * blockDim.x + threadIdx.x) >> 5;
    int lane = threadIdx.x & 31;
    if (warp >= MDEC) return;
    float acc[NOUT];
    #pragma unroll
    for (int o = 0; o < NOUT; o++) acc[o] = 0.f;
    const float* a = g_mid + (size_t)warp * HH;
    for (int k = lane; k < HH; k += 32) {
        float av = a[k];
        #pragma unroll
        for (int o = 0; o < NOUT; o++) acc[o] += av * w[o * HH + k];
    }
    #pragma unroll
    for (int o = 0; o < NOUT; o++) {
        #pragma unroll
        for (int sh = 16; sh > 0; sh >>= 1)
            acc[o] += __shfl_down_sync(0xffffffffu, acc[o], sh);
    }
    if (lane == 0) {
        #pragma unroll
        for (int o = 0; o < NOUT; o++) out[warp * NOUT + o] = acc[o] + bias[o];
    }
}

// ---------------- host orchestration ----------------
static inline dim3 gemm_grid(int M, int N) {
    return dim3((N + BN - 1) / BN, (M + BM - 1) / BM, 1);
}

template<typename T> static float* devptr(T& sym) {
    void* p = nullptr;
    cudaGetSymbolAddress(&p, sym);
    return (float*)p;
}

static void round_arr(const float* src, float* dst, int n) {
    int n4 = n / 4;
    round4_kernel<<<(n4 + 255)/256, 256>>>((const float4*)src, (float4*)dst, n4);
}

extern "C" void kernel_launch(void* const* d_in, const int* in_sizes, int n_in,
                              void* d_out, int out_size)
{
    const float* x_src    = (const float*)d_in[0];
    const float* y_src    = (const float*)d_in[1];
    const float* enc_w    = (const float*)d_in[2];
    const float* enc_b    = (const float*)d_in[3];
    const float* yenc_w   = (const float*)d_in[4];
    const float* yenc_b   = (const float*)d_in[5];
    const float* norm_w   = (const float*)d_in[6];
    const float* norm_b   = (const float*)d_in[7];
    const float* in_proj_w= (const float*)d_in[8];
    const float* conv_w   = (const float*)d_in[9];
    const float* conv_b   = (const float*)d_in[10];
    const float* x_proj_w = (const float*)d_in[11];
    const float* dt_w     = (const float*)d_in[12];
    const float* dt_b     = (const float*)d_in[13];
    const float* A_log    = (const float*)d_in[14];
    const float* D_ssm    = (const float*)d_in[15];
    const float* out_w    = (const float*)d_in[16];
    const float* normf_w  = (const float*)d_in[17];
    const float* normf_b  = (const float*)d_in[18];
    const float* dec1_w   = (const float*)d_in[19];
    const float* dec1_b   = (const float*)d_in[20];
    const float* dec2_w   = (const float*)d_in[21];
    const float* dec2_b   = (const float*)d_in[22];
    float* out = (float*)d_out;

    float* p_xT   = devptr(g_xT);
    float* p_h    = devptr(g_h);
    float* p_res  = devptr(g_res);
    float* p_hn   = devptr(g_hn);
    float* p_xz   = devptr(g_xz);
    float* p_xcr  = devptr(g_xcr);
    float* p_xdbl = devptr(g_xdbl);
    float* p_xpart= devptr(g_xpart);
    float* p_y    = devptr(g_y);
    float* p_dec  = devptr(g_dec);
    float* p_mid  = devptr(g_mid);
    float* pw_enc = devptr(w_enc);
    float* pw_inp = devptr(w_inp);
    float* pw_xp  = devptr(w_xp);
    float* pw_dtw = devptr(w_dtw);
    float* pw_out = devptr(w_outw);
    float* pw_d1  = devptr(w_dec1);

    // one-shot weight rounding (cheap, graph-captured)
    round_arr(enc_w,    pw_enc, DD*FF);
    round_arr(in_proj_w,pw_inp, NLAYER*2*DI*DD);
    round_arr(x_proj_w, pw_xp,  NLAYER*XP*DI);
    round_arr(dt_w,     pw_dtw, NLAYER*DI*RR);
    round_arr(out_w,    pw_out, NLAYER*DD*DI);
    round_arr(dec1_w,   pw_d1,  HH*DD);

    gather_x_kernel<<<(MROWS*FF + 255)/256, 256>>>(x_src);
    tgemm_tn<0><<<gemm_grid(MROWS, DD), 256>>>(p_xT, pw_enc, enc_b, p_h,
                                               MROWS, DD, FF, FF, FF, DD, 0);
    add_yenc_kernel<<<(MROWS*DD + 255)/256, 256>>>(y_src, yenc_w, yenc_b);

    for (int i = 0; i < NLAYER; i++) {
        resln_kernel<<<MROWS, 256>>>(p_h, p_res, p_hn,
                                     norm_w + i*DD, norm_b + i*DD, i == 0);
        tgemm_tn<0><<<gemm_grid(MROWS, 2*DI), 256>>>(
            p_hn, pw_inp + (size_t)i * (2*DI) * DD, nullptr, p_xz,
            MROWS, 2*DI, DD, DD, DD, 2*DI, 0);
        conv_silu_kernel<<<(MROWS*DI + 255)/256, 256>>>(conv_w + i*DI*KCONV, conv_b + i*DI);
        // x_proj split-K=4
        {
            dim3 g = gemm_grid(MROWS, XP);
            g.z = KSPLIT;
            tgemm_tn<0><<<g, 256>>>(
                p_xcr, pw_xp + (size_t)i * XP * DI, nullptr, p_xpart,
                MROWS, XP, DI / KSPLIT, DI, DI, XP, (size_t)MROWS * XP);
        }
        xproj_reduce_kernel<<<(MROWS*XP + 255)/256, 256>>>();
        tgemm_tn<1><<<gemm_grid(MROWS, DI), 256>>>(
            p_xdbl, pw_dtw + (size_t)i * DI * RR, dt_b + i*DI, devptr(g_dt),
            MROWS, DI, RR, XP, RR, DI, 0);
        scan_local_kernel  <<<(BB*DI*NCH + 255)/256, 256>>>(A_log + (size_t)i * DI * NST);
        scan_combine_kernel<<<(BB*DI     + 255)/256, 256>>>(A_log + (size_t)i * DI * NST);
        scan_final_kernel  <<<(BB*DI*NCH + 255)/256, 256>>>(A_log + (size_t)i * DI * NST,
                                                            D_ssm + i*DI);
        tgemm_tn<0><<<gemm_grid(MROWS, DD), 256>>>(
            p_y, pw_out + (size_t)i * DD * DI, nullptr, p_h,
            MROWS, DD, DI, DI, DI, DD, 0);
    }

    resln_kernel<<<MROWS, 256>>>(p_h, p_res, p_hn, normf_w, normf_b, 0);

    gather_dec_kernel<<<(MDEC*DD + 255)/256, 256>>>();
    tgemm_tn<2><<<gemm_grid(MDEC, HH), 256>>>(p_dec, pw_d1, dec1_b, p_mid,
                                              MDEC, HH, DD, DD, DD, HH, 0);
    dec2_kernel<<<(MDEC*32 + 255)/256, 256>>>(dec2_w, dec2_b, out);
}